// round 6
// baseline (speedup 1.0000x reference)
#include <cuda_runtime.h>
#include <cuda_bf16.h>
#include <math.h>
#include <stdint.h>

#define AN 4096
#define CN 8
#define FN 64
#define NTHREADS 256

// ---------------- device scratch (no allocation allowed) --------------------
__device__ float          g_xn[CN * AN * FN];       // [c][a][f] normalized fp32
__device__ __nv_bfloat16  g_xp[CN * AN * 64];       // [c][a][f] bf16 (hi only)
__device__ ulonglong2     g_stage[CN * 32 * 34 * 128];  // [c][jblk][slot][row] top2 keys
__device__ ulonglong2     g_top[CN * AN];           // merged top2 per row
__device__ float          g_partial[256];
__device__ unsigned int   g_done;

// ---------------- PTX helpers (generic sm_80+ ISA only) ---------------------
static __device__ __forceinline__ uint32_t smem_u32(const void* p) {
    uint32_t a;
    asm("{ .reg .u64 t; cvta.to.shared.u64 t, %1; cvt.u32.u64 %0, t; }"
        : "=r"(a) : "l"(p));
    return a;
}

#define CP16(dst, src) \
    asm volatile("cp.async.cg.shared.global [%0], [%1], 16;" :: "r"(dst), "l"(src))
#define CP_COMMIT() asm volatile("cp.async.commit_group;" ::: "memory")
#define CP_WAIT0()  asm volatile("cp.async.wait_group 0;" ::: "memory")
#define CP_WAIT1()  asm volatile("cp.async.wait_group 1;" ::: "memory")

static __device__ __forceinline__ void ldsm_x4(uint32_t* d, uint32_t addr) {
    asm volatile("ldmatrix.sync.aligned.m8n8.x4.shared.b16 {%0,%1,%2,%3}, [%4];"
                 : "=r"(d[0]), "=r"(d[1]), "=r"(d[2]), "=r"(d[3]) : "r"(addr));
}

static __device__ __forceinline__ void mma_bf16(float* c, const uint32_t* a,
                                                const uint32_t* b) {
    asm volatile(
        "mma.sync.aligned.m16n8k16.row.col.f32.bf16.bf16.f32 "
        "{%0,%1,%2,%3}, {%4,%5,%6,%7}, {%8,%9}, {%0,%1,%2,%3};"
        : "+f"(c[0]), "+f"(c[1]), "+f"(c[2]), "+f"(c[3])
        : "r"(a[0]), "r"(a[1]), "r"(a[2]), "r"(a[3]), "r"(b[0]), "r"(b[1]));
}

// swizzled byte offset of 16B chunk (r, ch) in a 128-row x 128B tile
static __device__ __forceinline__ uint32_t swz128(uint32_t r, uint32_t ch) {
    return r * 128u + ((ch ^ (r & 7u)) << 4);
}

// order-preserving float->u32, packed with (4095 - idx): u64-max picks
// (max value, then min index) — jnp.argmax first-index tie-break.
static __device__ __forceinline__ unsigned long long pack_key(float v, int idx) {
    uint32_t u = __float_as_uint(v);
    u = (u & 0x80000000u) ? ~u : (u | 0x80000000u);
    return ((unsigned long long)u << 32) | (uint32_t)(4095 - idx);
}

// top-2 merge of two (k1>=k2) pairs over disjoint candidate sets
static __device__ __forceinline__ void merge2(unsigned long long& a1,
                                              unsigned long long& a2,
                                              unsigned long long b1,
                                              unsigned long long b2) {
    if (b1 > a1) { a2 = (a1 > b2) ? a1 : b2; a1 = b1; }
    else         { a2 = (a2 > b1) ? a2 : b1; }
}

// ---------------------------------------------------------------------------
// Kernel 1: normalize rows -> fp32 (c-major) + bf16 row; reset g_done
// ---------------------------------------------------------------------------
__global__ void k_normalize(const float* __restrict__ x) {
    int gtid = blockIdx.x * blockDim.x + threadIdx.x;
    if (gtid == 0) g_done = 0;
    int warp = gtid >> 5;
    int lane = threadIdx.x & 31;
    if (warp >= AN * CN) return;
    int a = warp / CN;
    int c = warp % CN;
    const float2* row = (const float2*)(x + ((size_t)a * CN + c) * FN);
    float2 v = row[lane];
    float ss = v.x * v.x + v.y * v.y;
    #pragma unroll
    for (int o = 16; o > 0; o >>= 1) ss += __shfl_xor_sync(0xffffffffu, ss, o);
    float inv = 1.0f / fmaxf(sqrtf(ss), 1e-6f);
    float nx = v.x * inv, ny = v.y * inv;

    float2* dst = (float2*)(g_xn + ((size_t)c * AN + a) * FN);
    dst[lane] = make_float2(nx, ny);

    __nv_bfloat162 h2;
    h2.x = __float2bfloat16(nx);
    h2.y = __float2bfloat16(ny);
    ((__nv_bfloat162*)(g_xp + ((size_t)c * AN + a) * 64))[lane] = h2;
}

// ---------------------------------------------------------------------------
// Kernel 2: symmetric 1-term bf16 screening GEMM, top-2 per row AND col,
// staged to unique slots (no atomics). CTA = (strip-pair p, half h, chan c).
// ---------------------------------------------------------------------------
#define SM_A    0
#define SM_B0   16384
#define SM_B1   32768
#define SM_CS   49152      // col stage: 2*128 ulonglong2 = 4 KB
#define SM_RED  53248      // row reduce: 128*4 ulonglong2 = 8 KB
#define SMEM_BYTES 61440

extern __shared__ __align__(1024) uint8_t dsm[];

__global__ __launch_bounds__(NTHREADS, 2) void k_screen() {
    uint32_t sb = smem_u32(dsm);
    int tid = threadIdx.x;
    int lane = tid & 31;
    int wid = tid >> 5;
    int wm = wid >> 2;
    int wn = wid & 3;
    int p = blockIdx.x >> 1;
    int h = blockIdx.x & 1;
    int c = blockIdx.y;
    int i1 = p, i2 = 31 - p, n1 = 32 - p;

    const char* xc = (const char*)(g_xp + (size_t)c * AN * 64);  // 128B rows

    uint32_t a_rl = (uint32_t)((lane & 7) + ((lane >> 3) & 1) * 8);
    uint32_t a_cs = (uint32_t)(lane >> 4);
    uint32_t b_nl = (uint32_t)((lane & 7) + (lane >> 4) * 8);
    uint32_t b_cs = (uint32_t)((lane >> 3) & 1);
    uint32_t arow = (uint32_t)(wm * 64);

    float rv1[8], rv2[8];
    int   ri1[8], ri2[8];
    #pragma unroll
    for (int s = 0; s < 8; s++) { rv1[s] = -3.0f; rv2[s] = -3.0f; ri1[s] = 0; ri2[s] = 0; }

    auto flush_rows = [&](int fi) {
        ulonglong2* red = (ulonglong2*)(dsm + SM_RED);
        #pragma unroll
        for (int mi = 0; mi < 4; mi++) {
            #pragma unroll
            for (int hh = 0; hh < 2; hh++) {
                int s = mi * 2 + hh;
                unsigned long long k1 = pack_key(rv1[s], ri1[s]);
                unsigned long long k2 = pack_key(rv2[s], ri2[s]);
                #pragma unroll
                for (int o = 2; o > 0; o >>= 1) {
                    unsigned long long o1 = __shfl_down_sync(0xffffffffu, k1, o, 4);
                    unsigned long long o2 = __shfl_down_sync(0xffffffffu, k2, o, 4);
                    merge2(k1, k2, o1, o2);
                }
                if ((lane & 3) == 0) {
                    int lrow = wm * 64 + mi * 16 + (lane >> 2) + hh * 8;
                    red[lrow * 4 + wn] = make_ulonglong2(k1, k2);
                }
            }
        }
        __syncthreads();
        if (tid < 128) {
            ulonglong2 a = red[tid * 4];
            #pragma unroll
            for (int w = 1; w < 4; w++) {
                ulonglong2 b = red[tid * 4 + w];
                merge2(a.x, a.y, b.x, b.y);
            }
            g_stage[(((size_t)c * 32 + fi) * 34 + 32 + h) * 128 + tid] = a;
        }
        __syncthreads();
    };

    // ---- prologue: A(i1) + first B tile ----
    int curi = i1;
    {
        int j0 = p + h;
        #pragma unroll
        for (int u = 0; u < 4; u++) {
            int s = tid + u * NTHREADS;          // 0..1023
            uint32_t r = (uint32_t)(s >> 3), ch = (uint32_t)(s & 7);
            CP16(sb + SM_A  + swz128(r, ch), xc + (size_t)(i1 * 128 + r) * 128 + ch * 16);
            CP16(sb + SM_B0 + swz128(r, ch), xc + (size_t)(j0 * 128 + r) * 128 + ch * 16);
        }
        CP_COMMIT();
    }

    int it = 0;
    for (int jj = h; jj < 33; jj += 2, it++) {
        int i = (jj < n1) ? i1 : i2;
        int j = (jj < n1) ? (p + jj) : (i2 + (jj - n1));
        bool diag = (i == j);
        uint32_t bufc = sb + ((it & 1) ? SM_B1 : SM_B0);

        if (i != curi) {            // strip switch: flush rows, load new A
            flush_rows(curi);
            #pragma unroll
            for (int s = 0; s < 8; s++) { rv1[s] = -3.0f; rv2[s] = -3.0f; ri1[s] = 0; ri2[s] = 0; }
            #pragma unroll
            for (int u = 0; u < 4; u++) {
                int s = tid + u * NTHREADS;
                uint32_t r = (uint32_t)(s >> 3), ch = (uint32_t)(s & 7);
                CP16(sb + SM_A + swz128(r, ch),
                     xc + (size_t)(i * 128 + r) * 128 + ch * 16);
            }
            CP_COMMIT();
            curi = i;
        }

        int jj2 = jj + 2;
        if (jj2 < 33) {             // prefetch next B
            int jn = (jj2 < n1) ? (p + jj2) : (i2 + (jj2 - n1));
            uint32_t bufn = sb + ((it & 1) ? SM_B0 : SM_B1);
            #pragma unroll
            for (int u = 0; u < 4; u++) {
                int s = tid + u * NTHREADS;
                uint32_t r = (uint32_t)(s >> 3), ch = (uint32_t)(s & 7);
                CP16(bufn + swz128(r, ch),
                     xc + (size_t)(jn * 128 + r) * 128 + ch * 16);
            }
            CP_COMMIT();
            CP_WAIT1();             // everything except the fresh prefetch done
        } else {
            CP_WAIT0();
        }
        __syncthreads();

        // ---- compute + epilogue, split into two 16-col halves ----
        #pragma unroll
        for (int nh = 0; nh < 2; nh++) {
            float acc[4][2][4];
            #pragma unroll
            for (int mi = 0; mi < 4; mi++)
                #pragma unroll
                for (int ni = 0; ni < 2; ni++)
                    #pragma unroll
                    for (int q = 0; q < 4; q++) acc[mi][ni][q] = 0.0f;

            #pragma unroll
            for (int ks = 0; ks < 4; ks++) {
                uint32_t af[4][4], bf[4];
                #pragma unroll
                for (int mi = 0; mi < 4; mi++)
                    ldsm_x4(af[mi], sb + SM_A +
                            swz128(arow + (uint32_t)(mi * 16) + a_rl, (uint32_t)(2 * ks) + a_cs));
                ldsm_x4(bf, bufc +
                        swz128((uint32_t)(wn * 32 + nh * 16) + b_nl, (uint32_t)(2 * ks) + b_cs));
                #pragma unroll
                for (int mi = 0; mi < 4; mi++) {
                    mma_bf16(acc[mi][0], af[mi], &bf[0]);
                    mma_bf16(acc[mi][1], af[mi], &bf[2]);
                }
            }

            float cv1[4], cv2[4];
            int   ci1[4], ci2[4];
            #pragma unroll
            for (int s = 0; s < 4; s++) { cv1[s] = -3.0f; cv2[s] = -3.0f; ci1[s] = 0; ci2[s] = 0; }

            #pragma unroll
            for (int ni = 0; ni < 2; ni++) {
                #pragma unroll
                for (int q = 0; q < 2; q++) {
                    int cs = ni * 2 + q;
                    int cc = wn * 32 + nh * 16 + ni * 8 + (lane & 3) * 2 + q;
                    int gcol = j * 128 + cc;
                    #pragma unroll
                    for (int mi = 0; mi < 4; mi++) {
                        #pragma unroll
                        for (int hh = 0; hh < 2; hh++) {
                            int s = mi * 2 + hh;
                            int lrow = wm * 64 + mi * 16 + (lane >> 2) + hh * 8;
                            float v = acc[mi][ni][hh * 2 + q];
                            if (diag && cc == lrow) v = -2.0f;
                            if (v > rv2[s]) {
                                if (v > rv1[s]) { rv2[s] = rv1[s]; ri2[s] = ri1[s];
                                                  rv1[s] = v;      ri1[s] = gcol; }
                                else            { rv2[s] = v;      ri2[s] = gcol; }
                            }
                            int grow = curi * 128 + lrow;
                            if (v > cv2[cs]) {
                                if (v > cv1[cs]) { cv2[cs] = cv1[cs]; ci2[cs] = ci1[cs];
                                                   cv1[cs] = v;       ci1[cs] = grow; }
                                else             { cv2[cs] = v;       ci2[cs] = grow; }
                            }
                        }
                    }
                }
            }

            // col top-2 tree over the 8 row-groups (lanes sharing lane&3)
            #pragma unroll
            for (int cs = 0; cs < 4; cs++) {
                unsigned long long k1 = pack_key(cv1[cs], ci1[cs]);
                unsigned long long k2 = pack_key(cv2[cs], ci2[cs]);
                #pragma unroll
                for (int o = 16; o >= 4; o >>= 1) {
                    unsigned long long o1 = __shfl_down_sync(0xffffffffu, k1, o);
                    unsigned long long o2 = __shfl_down_sync(0xffffffffu, k2, o);
                    merge2(k1, k2, o1, o2);
                }
                if (lane < 4) {
                    int cc = wn * 32 + nh * 16 + (cs >> 1) * 8 + lane * 2 + (cs & 1);
                    ((ulonglong2*)(dsm + SM_CS))[wm * 128 + cc] = make_ulonglong2(k1, k2);
                }
            }
        }
        __syncthreads();
        if (!diag && tid < 128) {
            ulonglong2 x0 = ((ulonglong2*)(dsm + SM_CS))[tid];
            ulonglong2 x1 = ((ulonglong2*)(dsm + SM_CS))[128 + tid];
            merge2(x0.x, x0.y, x1.x, x1.y);
            g_stage[(((size_t)c * 32 + j) * 34 + curi) * 128 + tid] = x0;
        }
        __syncthreads();
    }

    flush_rows(curi);
    if (curi == i1 && tid < 128) {   // CTA never reached strip i2: stage sentinels
        unsigned long long sk = pack_key(-2.0f, 0);
        g_stage[(((size_t)c * 32 + i2) * 34 + 32 + h) * 128 + tid] = make_ulonglong2(sk, sk);
    }
}

// ---------------------------------------------------------------------------
// Kernel 3: merge staged top-2 pairs per row (slots 32,33 + cols 0..j-1)
// ---------------------------------------------------------------------------
__global__ void k_merge() {
    int g = blockIdx.x * blockDim.x + threadIdx.x;
    if (g >= CN * AN) return;
    int c = g >> 12, a = g & 4095, j = a >> 7, row = a & 127;
    const ulonglong2* base = g_stage + ((size_t)c * 32 + j) * 34 * 128;
    ulonglong2 acc = base[32 * 128 + row];
    ulonglong2 b = base[33 * 128 + row];
    merge2(acc.x, acc.y, b.x, b.y);
    for (int i = 0; i < j; i++) {
        b = base[i * 128 + row];
        merge2(acc.x, acc.y, b.x, b.y);
    }
    g_top[g] = acc;
}

// ---------------------------------------------------------------------------
// Kernel 4: exact fp32 refinement of top-2 + distance + loss (final fused)
// ---------------------------------------------------------------------------
__global__ void k_dist(float* __restrict__ out) {
    int gwarp  = (blockIdx.x * blockDim.x + threadIdx.x) >> 5;
    int lane   = threadIdx.x & 31;
    int nwarps = (gridDim.x * blockDim.x) >> 5;
    float acc = 0.0f;
    for (int item = gwarp; item < CN * AN; item += nwarps) {
        ulonglong2 k = g_top[item];
        int iA = 4095 - (int)(uint32_t)(k.x & 0xFFFFFFFFull);
        int iB = 4095 - (int)(uint32_t)(k.y & 0xFFFFFFFFull);
        int c = item >> 12;
        const float2* pa = (const float2*)(g_xn + (size_t)item * FN);
        const float2* p1 = (const float2*)(g_xn + ((size_t)c * AN + iA) * FN);
        const float2* p2 = (const float2*)(g_xn + ((size_t)c * AN + iB) * FN);
        float2 va = pa[lane], v1 = p1[lane], v2 = p2[lane];
        float s1 = va.x * v1.x + va.y * v1.y;
        float s2 = va.x * v2.x + va.y * v2.y;
        #pragma unroll
        for (int o = 16; o > 0; o >>= 1) {
            s1 += __shfl_xor_sync(0xffffffffu, s1, o);
            s2 += __shfl_xor_sync(0xffffffffu, s2, o);
        }
        bool useA = (s1 > s2) || (s1 == s2 && iA < iB);
        float2 vb = useA ? v1 : v2;
        float dx = va.x - vb.x + 1e-6f;
        float dy = va.y - vb.y + 1e-6f;
        float ss = dx * dx + dy * dy;
        #pragma unroll
        for (int o = 16; o > 0; o >>= 1) ss += __shfl_xor_sync(0xffffffffu, ss, o);
        if (lane == 0) acc -= logf(sqrtf(ss) + 1e-6f);
    }
    __shared__ float wsum[8];
    __shared__ float smf[256];
    if (lane == 0) wsum[threadIdx.x >> 5] = acc;
    __syncthreads();
    if (threadIdx.x == 0) {
        float s = 0.0f;
        #pragma unroll
        for (int i = 0; i < 8; i++) s += wsum[i];
        g_partial[blockIdx.x] = s;
        __threadfence();
        unsigned t = atomicInc(&g_done, 0xFFFFFFFFu);
        wsum[0] = (t == gridDim.x - 1) ? 1.0f : 0.0f;
    }
    __syncthreads();
    if (wsum[0] != 0.0f) {           // last block: deterministic final sum
        smf[threadIdx.x] = g_partial[threadIdx.x];
        __syncthreads();
        for (int s = 128; s > 0; s >>= 1) {
            if (threadIdx.x < s) smf[threadIdx.x] += smf[threadIdx.x + s];
            __syncthreads();
        }
        if (threadIdx.x == 0) out[0] = smf[0] / (float)(CN * AN);
    }
}

// ---------------------------------------------------------------------------
extern "C" void kernel_launch(void* const* d_in, const int* in_sizes, int n_in,
                              void* d_out, int out_size) {
    const float* x = (const float*)d_in[0];
    float* out = (float*)d_out;
    (void)in_sizes; (void)n_in; (void)out_size;

    cudaFuncSetAttribute(k_screen,
                         cudaFuncAttributeMaxDynamicSharedMemorySize, SMEM_BYTES);

    k_normalize<<<(AN * CN) / 8, NTHREADS>>>(x);
    k_screen<<<dim3(32, CN), NTHREADS, SMEM_BYTES>>>();
    k_merge<<<CN * AN / NTHREADS, NTHREADS>>>();
    k_dist<<<256, NTHREADS>>>(out);
}

// round 9
// speedup vs baseline: 1.3729x; 1.3729x over previous
#include <cuda_runtime.h>
#include <cuda_bf16.h>
#include <math.h>
#include <stdint.h>

#define AN 4096
#define CN 8
#define FN 64
#define NTHREADS 256
#define DIST_BLOCKS 1024

// ---------------- device scratch (no allocation allowed) --------------------
__device__ float          g_xn[CN * AN * FN];   // [c][a][f] normalized fp32
__device__ __nv_bfloat16  g_xp[CN * AN * 64];   // [c][a][f] bf16 (screen)
__device__ ulonglong2     g_top[CN * AN];       // top-2 packed keys per row
__device__ float          g_partial[DIST_BLOCKS];
__device__ unsigned int   g_done;

// ---------------- PTX helpers (generic sm_80+ ISA only) ---------------------
static __device__ __forceinline__ uint32_t smem_u32(const void* p) {
    uint32_t a;
    asm("{ .reg .u64 t; cvta.to.shared.u64 t, %1; cvt.u32.u64 %0, t; }"
        : "=r"(a) : "l"(p));
    return a;
}

#define CP16(dst, src) \
    asm volatile("cp.async.cg.shared.global [%0], [%1], 16;" :: "r"(dst), "l"(src))
#define CP_COMMIT() asm volatile("cp.async.commit_group;" ::: "memory")
#define CP_WAIT0()  asm volatile("cp.async.wait_group 0;" ::: "memory")
#define CP_WAIT1()  asm volatile("cp.async.wait_group 1;" ::: "memory")

static __device__ __forceinline__ void ldsm_x4(uint32_t* d, uint32_t addr) {
    asm volatile("ldmatrix.sync.aligned.m8n8.x4.shared.b16 {%0,%1,%2,%3}, [%4];"
                 : "=r"(d[0]), "=r"(d[1]), "=r"(d[2]), "=r"(d[3]) : "r"(addr));
}

static __device__ __forceinline__ void mma_bf16(float* c, const uint32_t* a,
                                                const uint32_t* b) {
    asm volatile(
        "mma.sync.aligned.m16n8k16.row.col.f32.bf16.bf16.f32 "
        "{%0,%1,%2,%3}, {%4,%5,%6,%7}, {%8,%9}, {%0,%1,%2,%3};"
        : "+f"(c[0]), "+f"(c[1]), "+f"(c[2]), "+f"(c[3])
        : "r"(a[0]), "r"(a[1]), "r"(a[2]), "r"(a[3]), "r"(b[0]), "r"(b[1]));
}

// swizzled byte offset of 16B chunk (r, ch) in a 128-row x 128B tile
static __device__ __forceinline__ uint32_t swz128(uint32_t r, uint32_t ch) {
    return r * 128u + ((ch ^ (r & 7u)) << 4);
}

// order-preserving float->u32, packed with (4095 - idx): u64-max picks
// (max value, then min index) — jnp.argmax first-index tie-break.
static __device__ __forceinline__ unsigned long long pack_key(float v, int idx) {
    uint32_t u = __float_as_uint(v);
    u = (u & 0x80000000u) ? ~u : (u | 0x80000000u);
    return ((unsigned long long)u << 32) | (uint32_t)(4095 - idx);
}

// top-2 merge of two sorted (k1>=k2) pairs over disjoint candidate sets
static __device__ __forceinline__ void merge2(unsigned long long& a1,
                                              unsigned long long& a2,
                                              unsigned long long b1,
                                              unsigned long long b2) {
    if (b1 > a1) { a2 = (a1 > b2) ? a1 : b2; a1 = b1; }
    else         { a2 = (a2 > b1) ? a2 : b1; }
}

// ---------------------------------------------------------------------------
// Kernel 1: normalize rows -> fp32 (c-major) + bf16 row; reset g_done
// ---------------------------------------------------------------------------
__global__ void k_normalize(const float* __restrict__ x) {
    int gtid = blockIdx.x * blockDim.x + threadIdx.x;
    if (gtid == 0) g_done = 0;
    int warp = gtid >> 5;
    int lane = threadIdx.x & 31;
    if (warp >= AN * CN) return;
    int a = warp / CN;
    int c = warp % CN;
    const float2* row = (const float2*)(x + ((size_t)a * CN + c) * FN);
    float2 v = row[lane];
    float ss = v.x * v.x + v.y * v.y;
    #pragma unroll
    for (int o = 16; o > 0; o >>= 1) ss += __shfl_xor_sync(0xffffffffu, ss, o);
    float inv = 1.0f / fmaxf(sqrtf(ss), 1e-6f);
    float nx = v.x * inv, ny = v.y * inv;

    float2* dst = (float2*)(g_xn + ((size_t)c * AN + a) * FN);
    dst[lane] = make_float2(nx, ny);

    __nv_bfloat162 h2;
    h2.x = __float2bfloat16(nx);
    h2.y = __float2bfloat16(ny);
    ((__nv_bfloat162*)(g_xp + ((size_t)c * AN + a) * 64))[lane] = h2;
}

// ---------------------------------------------------------------------------
// Kernel 2: 1-term bf16 screening GEMM, full sweep, top-2 per row in regs.
// CTA = 128 rows of one channel x all 32 col tiles. No atomics/staging:
// each CTA is the unique owner of its 128 rows -> direct g_top write.
// ---------------------------------------------------------------------------
#define SM_A    0
#define SM_B0   16384
#define SM_B1   32768
#define SM_RED  49152      // 128 rows x 4 warps x 16B = 8 KB
#define SMEM_BYTES 57344

extern __shared__ __align__(1024) uint8_t dsm[];

__global__ __launch_bounds__(NTHREADS, 2) void k_screen() {
    uint32_t sb = smem_u32(dsm);
    int tid = threadIdx.x;
    int lane = tid & 31;
    int wid = tid >> 5;
    int wm = wid >> 2;
    int wn = wid & 3;
    int c = blockIdx.y;
    int row0 = blockIdx.x * 128;

    const char* xc = (const char*)(g_xp + (size_t)c * AN * 64);  // 128B rows

    uint32_t a_rl = (uint32_t)((lane & 7) + ((lane >> 3) & 1) * 8);
    uint32_t a_cs = (uint32_t)(lane >> 4);
    uint32_t b_nl = (uint32_t)((lane & 7) + (lane >> 4) * 8);
    uint32_t b_cs = (uint32_t)((lane >> 3) & 1);
    uint32_t arow = (uint32_t)(wm * 64);

    float rv1[8], rv2[8];
    int   ri1[8], ri2[8];
    #pragma unroll
    for (int s = 0; s < 8; s++) { rv1[s] = -3.0f; rv2[s] = -4.0f; ri1[s] = 0; ri2[s] = 0; }

    // ---- prologue: A tile + B tile 0 ----
    #pragma unroll
    for (int u = 0; u < 4; u++) {
        int s = tid + u * NTHREADS;          // 0..1023
        uint32_t r = (uint32_t)(s >> 3), ch = (uint32_t)(s & 7);
        CP16(sb + SM_A  + swz128(r, ch), xc + (size_t)(row0 + r) * 128 + ch * 16);
        CP16(sb + SM_B0 + swz128(r, ch), xc + (size_t)r * 128 + ch * 16);
    }
    CP_COMMIT();

    for (int t = 0; t < 32; t++) {
        uint32_t bufc = sb + ((t & 1) ? SM_B1 : SM_B0);
        if (t + 1 < 32) {                    // prefetch next B
            uint32_t bufn = sb + ((t & 1) ? SM_B0 : SM_B1);
            const char* bsrc = xc + (size_t)(t + 1) * 128 * 128;
            #pragma unroll
            for (int u = 0; u < 4; u++) {
                int s = tid + u * NTHREADS;
                uint32_t r = (uint32_t)(s >> 3), ch = (uint32_t)(s & 7);
                CP16(bufn + swz128(r, ch), bsrc + (size_t)r * 128 + ch * 16);
            }
            CP_COMMIT();
            CP_WAIT1();                      // current tile's data resident
        } else {
            CP_WAIT0();
        }
        __syncthreads();

        // ---- 1-term MMA: 64x128x64 per warp pair layout (2m x 4n warps) ----
        float acc[4][4][4];
        #pragma unroll
        for (int mi = 0; mi < 4; mi++)
            #pragma unroll
            for (int ni = 0; ni < 4; ni++)
                #pragma unroll
                for (int q = 0; q < 4; q++) acc[mi][ni][q] = 0.0f;

        #pragma unroll
        for (int ks = 0; ks < 4; ks++) {
            uint32_t kc = (uint32_t)(ks * 2);
            uint32_t af[4][4], bf[2][4];
            #pragma unroll
            for (int mi = 0; mi < 4; mi++)
                ldsm_x4(af[mi], sb + SM_A + swz128(arow + (uint32_t)(mi * 16) + a_rl, kc + a_cs));
            #pragma unroll
            for (int nh = 0; nh < 2; nh++)
                ldsm_x4(bf[nh], bufc + swz128((uint32_t)(wn * 32 + nh * 16) + b_nl, kc + b_cs));
            #pragma unroll
            for (int mi = 0; mi < 4; mi++)
                #pragma unroll
                for (int ni = 0; ni < 4; ni++)
                    mma_bf16(acc[mi][ni], af[mi], &bf[ni >> 1][(ni & 1) * 2]);
        }

        // ---- epilogue: rows-only top-2 insert ----
        bool dt = (t == (int)blockIdx.x);
        #pragma unroll
        for (int mi = 0; mi < 4; mi++) {
            #pragma unroll
            for (int hh = 0; hh < 2; hh++) {
                int s = mi * 2 + hh;
                int lrow = wm * 64 + mi * 16 + (lane >> 2) + hh * 8;
                #pragma unroll
                for (int ni = 0; ni < 4; ni++) {
                    #pragma unroll
                    for (int q = 0; q < 2; q++) {
                        float v = acc[mi][ni][hh * 2 + q];
                        int cc = wn * 32 + ni * 8 + (lane & 3) * 2 + q;
                        if (dt && cc == lrow) v = -2.0f;
                        if (v > rv2[s]) {
                            if (v > rv1[s]) { rv2[s] = rv1[s]; ri2[s] = ri1[s];
                                              rv1[s] = v;      ri1[s] = t * 128 + cc; }
                            else            { rv2[s] = v;      ri2[s] = t * 128 + cc; }
                        }
                    }
                }
            }
        }
        __syncthreads();
    }

    // ---- final top-2 reduce: quad -> smem -> 4 wn warps -> g_top ----
    ulonglong2* red = (ulonglong2*)(dsm + SM_RED);
    #pragma unroll
    for (int mi = 0; mi < 4; mi++) {
        #pragma unroll
        for (int hh = 0; hh < 2; hh++) {
            int s = mi * 2 + hh;
            unsigned long long k1 = pack_key(rv1[s], ri1[s]);
            unsigned long long k2 = pack_key(rv2[s], ri2[s]);
            #pragma unroll
            for (int o = 2; o > 0; o >>= 1) {
                unsigned long long o1 = __shfl_down_sync(0xffffffffu, k1, o, 4);
                unsigned long long o2 = __shfl_down_sync(0xffffffffu, k2, o, 4);
                merge2(k1, k2, o1, o2);
            }
            if ((lane & 3) == 0) {
                int lrow = wm * 64 + mi * 16 + (lane >> 2) + hh * 8;
                red[lrow * 4 + wn] = make_ulonglong2(k1, k2);
            }
        }
    }
    __syncthreads();
    if (tid < 128) {
        ulonglong2 a = red[tid * 4];
        #pragma unroll
        for (int w = 1; w < 4; w++) {
            ulonglong2 b = red[tid * 4 + w];
            merge2(a.x, a.y, b.x, b.y);
        }
        g_top[(size_t)c * AN + row0 + tid] = a;
    }
}

// ---------------------------------------------------------------------------
// Kernel 3: exact fp32 top-2 refinement + distance + fused final reduction
// ---------------------------------------------------------------------------
__global__ void k_dist(float* __restrict__ out) {
    int gwarp  = (blockIdx.x * blockDim.x + threadIdx.x) >> 5;
    int lane   = threadIdx.x & 31;
    int nwarps = (gridDim.x * blockDim.x) >> 5;
    float acc = 0.0f;
    for (int item = gwarp; item < CN * AN; item += nwarps) {
        ulonglong2 k = g_top[item];
        int iA = 4095 - (int)(uint32_t)(k.x & 0xFFFFFFFFull);
        int iB = 4095 - (int)(uint32_t)(k.y & 0xFFFFFFFFull);
        int c = item >> 12;
        const float2* pa = (const float2*)(g_xn + (size_t)item * FN);
        const float2* p1 = (const float2*)(g_xn + ((size_t)c * AN + iA) * FN);
        const float2* p2 = (const float2*)(g_xn + ((size_t)c * AN + iB) * FN);
        float2 va = pa[lane], v1 = p1[lane], v2 = p2[lane];
        float s1 = va.x * v1.x + va.y * v1.y;
        float s2 = va.x * v2.x + va.y * v2.y;
        #pragma unroll
        for (int o = 16; o > 0; o >>= 1) {
            s1 += __shfl_xor_sync(0xffffffffu, s1, o);
            s2 += __shfl_xor_sync(0xffffffffu, s2, o);
        }
        bool useA = (s1 > s2) || (s1 == s2 && iA < iB);
        float2 vb = useA ? v1 : v2;
        float dx = va.x - vb.x + 1e-6f;
        float dy = va.y - vb.y + 1e-6f;
        float ss = dx * dx + dy * dy;
        #pragma unroll
        for (int o = 16; o > 0; o >>= 1) ss += __shfl_xor_sync(0xffffffffu, ss, o);
        if (lane == 0) acc -= logf(sqrtf(ss) + 1e-6f);
    }
    __shared__ float wsum[8];
    __shared__ float smf[256];
    if (lane == 0) wsum[threadIdx.x >> 5] = acc;
    __syncthreads();
    if (threadIdx.x == 0) {
        float s = 0.0f;
        #pragma unroll
        for (int i = 0; i < 8; i++) s += wsum[i];
        g_partial[blockIdx.x] = s;
        __threadfence();
        unsigned t = atomicInc(&g_done, 0xFFFFFFFFu);
        wsum[0] = (t == gridDim.x - 1) ? 1.0f : 0.0f;
    }
    __syncthreads();
    if (wsum[0] != 0.0f) {              // last block: deterministic final sum
        float s = 0.0f;
        #pragma unroll
        for (int u = 0; u < DIST_BLOCKS / 256; u++)
            s += g_partial[threadIdx.x + u * 256];
        smf[threadIdx.x] = s;
        __syncthreads();
        for (int st = 128; st > 0; st >>= 1) {
            if (threadIdx.x < st) smf[threadIdx.x] += smf[threadIdx.x + st];
            __syncthreads();
        }
        if (threadIdx.x == 0) out[0] = smf[0] / (float)(CN * AN);
    }
}

// ---------------------------------------------------------------------------
extern "C" void kernel_launch(void* const* d_in, const int* in_sizes, int n_in,
                              void* d_out, int out_size) {
    const float* x = (const float*)d_in[0];
    float* out = (float*)d_out;
    (void)in_sizes; (void)n_in; (void)out_size;

    cudaFuncSetAttribute(k_screen,
                         cudaFuncAttributeMaxDynamicSharedMemorySize, SMEM_BYTES);

    k_normalize<<<(AN * CN) / 8, NTHREADS>>>(x);
    k_screen<<<dim3(32, CN), NTHREADS, SMEM_BYTES>>>();
    k_dist<<<DIST_BLOCKS, NTHREADS>>>(out);
}

// round 12
// speedup vs baseline: 1.6749x; 1.2200x over previous
#include <cuda_runtime.h>
#include <cuda_bf16.h>
#include <math.h>
#include <stdint.h>

#define AN 4096
#define CN 8
#define FN 64
#define NTHREADS 256
#define DIST_BLOCKS 1024

// ---------------- device scratch (no allocation allowed) --------------------
__device__ float          g_xn[CN * AN * FN];   // [c][a][f] normalized fp32
__device__ __nv_bfloat16  g_xp[CN * AN * 64];   // [c][a][f] bf16 (screen)
__device__ ulonglong2     g_top[CN * AN];       // top-2 packed keys per row
__device__ float          g_partial[DIST_BLOCKS];
__device__ unsigned int   g_done;

// ---------------- PTX helpers (generic sm_80+ ISA only) ---------------------
static __device__ __forceinline__ uint32_t smem_u32(const void* p) {
    uint32_t a;
    asm("{ .reg .u64 t; cvta.to.shared.u64 t, %1; cvt.u32.u64 %0, t; }"
        : "=r"(a) : "l"(p));
    return a;
}

#define CP16(dst, src) \
    asm volatile("cp.async.cg.shared.global [%0], [%1], 16;" :: "r"(dst), "l"(src))
#define CP_COMMIT() asm volatile("cp.async.commit_group;" ::: "memory")
#define CP_WAIT0()  asm volatile("cp.async.wait_group 0;" ::: "memory")

static __device__ __forceinline__ void ldsm_x4(uint32_t* d, uint32_t addr) {
    asm volatile("ldmatrix.sync.aligned.m8n8.x4.shared.b16 {%0,%1,%2,%3}, [%4];"
                 : "=r"(d[0]), "=r"(d[1]), "=r"(d[2]), "=r"(d[3]) : "r"(addr));
}

static __device__ __forceinline__ void mma_bf16(float* c, const uint32_t* a,
                                                const uint32_t* b) {
    asm volatile(
        "mma.sync.aligned.m16n8k16.row.col.f32.bf16.bf16.f32 "
        "{%0,%1,%2,%3}, {%4,%5,%6,%7}, {%8,%9}, {%0,%1,%2,%3};"
        : "+f"(c[0]), "+f"(c[1]), "+f"(c[2]), "+f"(c[3])
        : "r"(a[0]), "r"(a[1]), "r"(a[2]), "r"(a[3]), "r"(b[0]), "r"(b[1]));
}

// swizzled byte offset of 16B chunk (r, ch) in a 128-row x 128B tile
static __device__ __forceinline__ uint32_t swz128(uint32_t r, uint32_t ch) {
    return r * 128u + ((ch ^ (r & 7u)) << 4);
}

// order-preserving float->u32, packed with (4095 - idx): u64-max picks
// (max value, then min index) — jnp.argmax first-index tie-break.
static __device__ __forceinline__ unsigned long long pack_key(float v, int idx) {
    uint32_t u = __float_as_uint(v);
    u = (u & 0x80000000u) ? ~u : (u | 0x80000000u);
    return ((unsigned long long)u << 32) | (uint32_t)(4095 - idx);
}

// top-2 merge of two sorted (k1>=k2) pairs over disjoint candidate sets
static __device__ __forceinline__ void merge2(unsigned long long& a1,
                                              unsigned long long& a2,
                                              unsigned long long b1,
                                              unsigned long long b2) {
    if (b1 > a1) { a2 = (a1 > b2) ? a1 : b2; a1 = b1; }
    else         { a2 = (a2 > b1) ? a2 : b1; }
}

// ---------------------------------------------------------------------------
// Kernel 1: normalize rows -> fp32 (c-major) + bf16 row; reset g_done
// ---------------------------------------------------------------------------
__global__ void k_normalize(const float* __restrict__ x) {
    int gtid = blockIdx.x * blockDim.x + threadIdx.x;
    if (gtid == 0) g_done = 0;
    int warp = gtid >> 5;
    int lane = threadIdx.x & 31;
    if (warp >= AN * CN) return;
    int a = warp / CN;
    int c = warp % CN;
    const float2* row = (const float2*)(x + ((size_t)a * CN + c) * FN);
    float2 v = row[lane];
    float ss = v.x * v.x + v.y * v.y;
    #pragma unroll
    for (int o = 16; o > 0; o >>= 1) ss += __shfl_xor_sync(0xffffffffu, ss, o);
    float inv = 1.0f / fmaxf(sqrtf(ss), 1e-6f);
    float nx = v.x * inv, ny = v.y * inv;

    float2* dst = (float2*)(g_xn + ((size_t)c * AN + a) * FN);
    dst[lane] = make_float2(nx, ny);

    __nv_bfloat162 h2;
    h2.x = __float2bfloat16(nx);
    h2.y = __float2bfloat16(ny);
    ((__nv_bfloat162*)(g_xp + ((size_t)c * AN + a) * 64))[lane] = h2;
}

// ---------------------------------------------------------------------------
// Kernel 2: 1-term bf16 screening GEMM, full sweep, top-2 per row in regs.
// Deferred-fold epilogue: tile t's candidate extraction executes at the top
// of tile t+1, interleaved with fresh HMMA issue (tensor pipe stays fed).
// ---------------------------------------------------------------------------
#define SM_A    0
#define SM_B0   16384
#define SM_B1   32768
#define SM_RED  49152      // 128 rows x 4 warps x 16B = 8 KB
#define SMEM_BYTES 57344

extern __shared__ __align__(1024) uint8_t dsm[];

__global__ __launch_bounds__(NTHREADS, 2) void k_screen() {
    uint32_t sb = smem_u32(dsm);
    int tid = threadIdx.x;
    int lane = tid & 31;
    int wid = tid >> 5;
    int wm = wid >> 2;
    int wn = wid & 3;
    int c = blockIdx.y;
    int row0 = blockIdx.x * 128;

    const char* xc = (const char*)(g_xp + (size_t)c * AN * 64);  // 128B rows

    uint32_t a_rl = (uint32_t)((lane & 7) + ((lane >> 3) & 1) * 8);
    uint32_t a_cs = (uint32_t)(lane >> 4);
    uint32_t b_nl = (uint32_t)((lane & 7) + (lane >> 4) * 8);
    uint32_t b_cs = (uint32_t)((lane >> 3) & 1);
    uint32_t arow = (uint32_t)(wm * 64);

    float rv1[8], rv2[8];
    int   ri1[8], ri2[8];
    #pragma unroll
    for (int s = 0; s < 8; s++) { rv1[s] = -3.0f; rv2[s] = -4.0f; ri1[s] = 0; ri2[s] = 0; }

    float acc[4][4][4];

    // fold tile pt's accumulators into the running top-2 (branchless).
    // MASKDIAG: exclude the self column (only the diagonal tile needs it).
    auto fold = [&](int pt, bool maskdiag) {
        #pragma unroll
        for (int mi = 0; mi < 4; mi++) {
            #pragma unroll
            for (int hh = 0; hh < 2; hh++) {
                int s = mi * 2 + hh;
                int lrow = wm * 64 + mi * 16 + (lane >> 2) + hh * 8;
                float bv = -5.0f;
                int   bc = 0;
                #pragma unroll
                for (int ni = 0; ni < 4; ni++) {
                    #pragma unroll
                    for (int q = 0; q < 2; q++) {
                        float v = acc[mi][ni][hh * 2 + q];
                        if (maskdiag) {
                            int cc = wn * 32 + ni * 8 + (lane & 3) * 2 + q;
                            v = (cc == lrow) ? -2.0f : v;
                        }
                        int code = ni * 2 + q;       // ascending col within thread
                        bool g = v > bv;             // strict > keeps first (lowest col)
                        bv = g ? v : bv;
                        bc = g ? code : bc;
                    }
                }
                int idx = pt * 128 + wn * 32 + (bc >> 1) * 8 + (lane & 3) * 2 + (bc & 1);
                bool g1 = bv > rv1[s];
                bool g2 = bv > rv2[s];
                ri2[s] = g1 ? ri1[s] : (g2 ? idx : ri2[s]);
                rv2[s] = g1 ? rv1[s] : (g2 ? bv : rv2[s]);
                ri1[s] = g1 ? idx : ri1[s];
                rv1[s] = g1 ? bv : rv1[s];
            }
        }
    };

    // ---- prologue: A tile + B tile 0 (one cp.async group) ----
    #pragma unroll
    for (int u = 0; u < 4; u++) {
        int s = tid + u * NTHREADS;          // 0..1023
        uint32_t r = (uint32_t)(s >> 3), ch = (uint32_t)(s & 7);
        CP16(sb + SM_A  + swz128(r, ch), xc + (size_t)(row0 + r) * 128 + ch * 16);
        CP16(sb + SM_B0 + swz128(r, ch), xc + (size_t)r * 128 + ch * 16);
    }
    CP_COMMIT();

    for (int t = 0; t < 32; t++) {
        CP_WAIT0();          // tile t's data landed (this thread's group)
        __syncthreads();     // publish to all warps + fence buffer reuse

        if (t + 1 < 32) {    // prefetch next B into the other buffer
            uint32_t bufn = sb + ((t & 1) ? SM_B0 : SM_B1);
            const char* bsrc = xc + (size_t)(t + 1) * 128 * 128;
            #pragma unroll
            for (int u = 0; u < 4; u++) {
                int s = tid + u * NTHREADS;
                uint32_t r = (uint32_t)(s >> 3), ch = (uint32_t)(s & 7);
                CP16(bufn + swz128(r, ch), bsrc + (size_t)r * 128 + ch * 16);
            }
            CP_COMMIT();
        }

        // deferred epilogue of tile t-1 — overlaps the HMMA issue below
        if (t > 0) {
            if (t - 1 == (int)blockIdx.x) fold(t - 1, true);
            else                          fold(t - 1, false);
        }

        // ---- MMA tile t ----
        #pragma unroll
        for (int mi = 0; mi < 4; mi++)
            #pragma unroll
            for (int ni = 0; ni < 4; ni++)
                #pragma unroll
                for (int q = 0; q < 4; q++) acc[mi][ni][q] = 0.0f;

        uint32_t bufc = sb + ((t & 1) ? SM_B1 : SM_B0);
        #pragma unroll
        for (int ks = 0; ks < 4; ks++) {
            uint32_t kc = (uint32_t)(ks * 2);
            uint32_t af[4][4], bf[2][4];
            #pragma unroll
            for (int mi = 0; mi < 4; mi++)
                ldsm_x4(af[mi], sb + SM_A + swz128(arow + (uint32_t)(mi * 16) + a_rl, kc + a_cs));
            #pragma unroll
            for (int nh = 0; nh < 2; nh++)
                ldsm_x4(bf[nh], bufc + swz128((uint32_t)(wn * 32 + nh * 16) + b_nl, kc + b_cs));
            #pragma unroll
            for (int mi = 0; mi < 4; mi++)
                #pragma unroll
                for (int ni = 0; ni < 4; ni++)
                    mma_bf16(acc[mi][ni], af[mi], &bf[ni >> 1][(ni & 1) * 2]);
        }
    }

    // fold the last tile (exposed — 1/32 of total)
    if (31 == (int)blockIdx.x) fold(31, true);
    else                       fold(31, false);

    // ---- final top-2 reduce: quad -> smem -> 4 wn warps -> g_top ----
    __syncthreads();
    ulonglong2* red = (ulonglong2*)(dsm + SM_RED);
    #pragma unroll
    for (int mi = 0; mi < 4; mi++) {
        #pragma unroll
        for (int hh = 0; hh < 2; hh++) {
            int s = mi * 2 + hh;
            unsigned long long k1 = pack_key(rv1[s], ri1[s]);
            unsigned long long k2 = pack_key(rv2[s], ri2[s]);
            #pragma unroll
            for (int o = 2; o > 0; o >>= 1) {
                unsigned long long o1 = __shfl_down_sync(0xffffffffu, k1, o, 4);
                unsigned long long o2 = __shfl_down_sync(0xffffffffu, k2, o, 4);
                merge2(k1, k2, o1, o2);
            }
            if ((lane & 3) == 0) {
                int lrow = wm * 64 + mi * 16 + (lane >> 2) + hh * 8;
                red[lrow * 4 + wn] = make_ulonglong2(k1, k2);
            }
        }
    }
    __syncthreads();
    if (tid < 128) {
        ulonglong2 a = red[tid * 4];
        #pragma unroll
        for (int w = 1; w < 4; w++) {
            ulonglong2 b = red[tid * 4 + w];
            merge2(a.x, a.y, b.x, b.y);
        }
        g_top[(size_t)c * AN + row0 + tid] = a;
    }
}

// ---------------------------------------------------------------------------
// Kernel 3: exact fp32 top-2 refinement + distance + fused final reduction
// ---------------------------------------------------------------------------
__global__ void k_dist(float* __restrict__ out) {
    int gwarp  = (blockIdx.x * blockDim.x + threadIdx.x) >> 5;
    int lane   = threadIdx.x & 31;
    int nwarps = (gridDim.x * blockDim.x) >> 5;
    float acc = 0.0f;
    for (int item = gwarp; item < CN * AN; item += nwarps) {
        ulonglong2 k = g_top[item];
        int iA = 4095 - (int)(uint32_t)(k.x & 0xFFFFFFFFull);
        int iB = 4095 - (int)(uint32_t)(k.y & 0xFFFFFFFFull);
        int c = item >> 12;
        const float2* pa = (const float2*)(g_xn + (size_t)item * FN);
        const float2* p1 = (const float2*)(g_xn + ((size_t)c * AN + iA) * FN);
        const float2* p2 = (const float2*)(g_xn + ((size_t)c * AN + iB) * FN);
        float2 va = pa[lane], v1 = p1[lane], v2 = p2[lane];
        float s1 = va.x * v1.x + va.y * v1.y;
        float s2 = va.x * v2.x + va.y * v2.y;
        #pragma unroll
        for (int o = 16; o > 0; o >>= 1) {
            s1 += __shfl_xor_sync(0xffffffffu, s1, o);
            s2 += __shfl_xor_sync(0xffffffffu, s2, o);
        }
        bool useA = (s1 > s2) || (s1 == s2 && iA < iB);
        float2 vb = useA ? v1 : v2;
        float dx = va.x - vb.x + 1e-6f;
        float dy = va.y - vb.y + 1e-6f;
        float ss = dx * dx + dy * dy;
        #pragma unroll
        for (int o = 16; o > 0; o >>= 1) ss += __shfl_xor_sync(0xffffffffu, ss, o);
        if (lane == 0) acc -= logf(sqrtf(ss) + 1e-6f);
    }
    __shared__ float wsum[8];
    __shared__ float smf[256];
    if (lane == 0) wsum[threadIdx.x >> 5] = acc;
    __syncthreads();
    if (threadIdx.x == 0) {
        float s = 0.0f;
        #pragma unroll
        for (int i = 0; i < 8; i++) s += wsum[i];
        g_partial[blockIdx.x] = s;
        __threadfence();
        unsigned t = atomicInc(&g_done, 0xFFFFFFFFu);
        wsum[0] = (t == gridDim.x - 1) ? 1.0f : 0.0f;
    }
    __syncthreads();
    if (wsum[0] != 0.0f) {              // last block: deterministic final sum
        float s = 0.0f;
        #pragma unroll
        for (int u = 0; u < DIST_BLOCKS / 256; u++)
            s += g_partial[threadIdx.x + u * 256];
        smf[threadIdx.x] = s;
        __syncthreads();
        for (int st = 128; st > 0; st >>= 1) {
            if (threadIdx.x < st) smf[threadIdx.x] += smf[threadIdx.x + st];
            __syncthreads();
        }
        if (threadIdx.x == 0) out[0] = smf[0] / (float)(CN * AN);
    }
}

// ---------------------------------------------------------------------------
extern "C" void kernel_launch(void* const* d_in, const int* in_sizes, int n_in,
                              void* d_out, int out_size) {
    const float* x = (const float*)d_in[0];
    float* out = (float*)d_out;
    (void)in_sizes; (void)n_in; (void)out_size;

    cudaFuncSetAttribute(k_screen,
                         cudaFuncAttributeMaxDynamicSharedMemorySize, SMEM_BYTES);

    k_normalize<<<(AN * CN) / 8, NTHREADS>>>(x);
    k_screen<<<dim3(32, CN), NTHREADS, SMEM_BYTES>>>();
    k_dist<<<DIST_BLOCKS, NTHREADS>>>(out);
}